// round 12
// baseline (speedup 1.0000x reference)
#include <cuda_runtime.h>

// Problem constants
#define NB    32
#define NH    64
#define NW    64
#define NT    100
#define COUT  8
#define KS    6
#define LP    2

#define TILE_W 16
#define TILE_H 8
#define HALO_W (TILE_W + KS - 1)   // 21
#define HALO_H (TILE_H + KS - 1)   // 13
#define NPIX   (HALO_W * HALO_H)   // 273
#define K1THR  128                 // one thread per output pixel
#define NCH    13                  // chunks 0..11: 8 timesteps, chunk 12: 4
#define NHWT   (NH * NW * NT)      // 409600
#define PSTRIDE 6                  // u64 per pixel (48B): 16B-aligned cp16, conflict-free LDS.128

typedef unsigned long long u64;

// scratch: Wx[b][c][h][w][t]  (419 MB static device array -- sanctioned scratch)
__device__ __align__(16) float g_wx[(size_t)NB * COUT * NH * NW * NT];

__device__ __forceinline__ void upk2(u64 v, float& lo, float& hi) {
    asm("mov.b64 {%0, %1}, %2;" : "=f"(lo), "=f"(hi) : "l"(v));
}
__device__ __forceinline__ u64 fma2(u64 a, u64 b, u64 c) {
    u64 d; asm("fma.rn.f32x2 %0, %1, %2, %3;" : "=l"(d) : "l"(a), "l"(b), "l"(c)); return d;
}
__device__ __forceinline__ unsigned smem_u32(const void* p) {
    return (unsigned)__cvta_generic_to_shared(p);
}
__device__ __forceinline__ void cp16(unsigned dst, const void* src) {
    asm volatile("cp.async.ca.shared.global [%0], [%1], 16;" :: "r"(dst), "l"(src));
}
__device__ __forceinline__ void cp_commit() { asm volatile("cp.async.commit_group;" ::: "memory"); }
__device__ __forceinline__ void cp_wait0()  { asm volatile("cp.async.wait_group 0;" ::: "memory"); }

// ============================ K1: convolution ============================
// One block per (w-tile, h-tile, b, chunk). No chunk loop, no recurrence.
__global__ __launch_bounds__(K1THR)
void k1_conv(const float* __restrict__ x,
             const float* __restrict__ w)
{
    __shared__ __align__(16) u64 sx[NPIX * PSTRIDE];
    __shared__ __align__(16) u64 sw2[KS * KS * COUT];   // tap-major, (w,w) duplicated

    const int tx    = threadIdx.x;
    const int ty    = threadIdx.y;
    const int tid   = tx + TILE_W * ty;
    const int b     = blockIdx.z / NCH;
    const int chunk = blockIdx.z % NCH;
    const int t0    = chunk * 8;
    const bool full = (chunk != NCH - 1);       // chunk 12 has 4 timesteps
    const int h0    = blockIdx.y * TILE_H;
    const int w0    = blockIdx.x * TILE_W;

    // weights: transpose [cout][tap] -> [tap][cout], duplicate into f32x2 lanes
    for (int i = tid; i < KS * KS * COUT; i += K1THR) {
        int tap = i >> 3, c = i & 7;
        unsigned bits = __float_as_uint(w[c * (KS * KS) + tap]);
        sw2[i] = ((u64)bits << 32) | (u64)bits;
    }

    // halo load: in-bounds via cp16, OOB zeroed directly
    const float* xb = x + (size_t)b * NH * NW * NT;
    const int n16 = full ? 2 : 1;
    for (int idx = tid; idx < NPIX * n16; idx += K1THR) {
        int pix = (n16 == 2) ? (idx >> 1) : idx;
        int j   = (n16 == 2) ? (idx & 1) : 0;
        int r = pix / HALO_W, c = pix % HALO_W;
        int gh = h0 - LP + r, gw = w0 - LP + c;
        if (gh >= 0 && gh < NH && gw >= 0 && gw < NW) {
            const float* src = xb + ((size_t)gh * NW + gw) * NT + t0 + j * 4;
            cp16(smem_u32(&sx[pix * PSTRIDE + j * 2]), src);
        } else {
            sx[pix * PSTRIDE + j * 2 + 0] = 0ull;
            sx[pix * PSTRIDE + j * 2 + 1] = 0ull;
        }
    }
    cp_commit();
    cp_wait0();
    __syncthreads();

    float* ob = g_wx + (size_t)b * COUT * NHWT
                     + ((size_t)(h0 + ty) * NW + (w0 + tx)) * NT + t0;

    // 8 couts x 4 (or 2) f32x2 accumulators
    u64 A0[COUT], A1[COUT], A2[COUT], A3[COUT];
#pragma unroll
    for (int c = 0; c < COUT; c++) { A0[c] = 0; A1[c] = 0; A2[c] = 0; A3[c] = 0; }

    if (full) {
#pragma unroll
        for (int kh = 0; kh < KS; kh++) {
#pragma unroll
            for (int kw = 0; kw < KS; kw++) {
                const int tap = kh * KS + kw;
                const u64* xp = &sx[((ty + kh) * HALO_W + (tx + kw)) * PSTRIDE];
                ulonglong2 xA = *(const ulonglong2*)(xp);
                ulonglong2 xB = *(const ulonglong2*)(xp + 2);
                ulonglong2 w01 = *(const ulonglong2*)&sw2[tap * COUT + 0];
                ulonglong2 w23 = *(const ulonglong2*)&sw2[tap * COUT + 2];
                ulonglong2 w45 = *(const ulonglong2*)&sw2[tap * COUT + 4];
                ulonglong2 w67 = *(const ulonglong2*)&sw2[tap * COUT + 6];
                A0[0] = fma2(xA.x, w01.x, A0[0]); A1[0] = fma2(xA.y, w01.x, A1[0]);
                A2[0] = fma2(xB.x, w01.x, A2[0]); A3[0] = fma2(xB.y, w01.x, A3[0]);
                A0[1] = fma2(xA.x, w01.y, A0[1]); A1[1] = fma2(xA.y, w01.y, A1[1]);
                A2[1] = fma2(xB.x, w01.y, A2[1]); A3[1] = fma2(xB.y, w01.y, A3[1]);
                A0[2] = fma2(xA.x, w23.x, A0[2]); A1[2] = fma2(xA.y, w23.x, A1[2]);
                A2[2] = fma2(xB.x, w23.x, A2[2]); A3[2] = fma2(xB.y, w23.x, A3[2]);
                A0[3] = fma2(xA.x, w23.y, A0[3]); A1[3] = fma2(xA.y, w23.y, A1[3]);
                A2[3] = fma2(xB.x, w23.y, A2[3]); A3[3] = fma2(xB.y, w23.y, A3[3]);
                A0[4] = fma2(xA.x, w45.x, A0[4]); A1[4] = fma2(xA.y, w45.x, A1[4]);
                A2[4] = fma2(xB.x, w45.x, A2[4]); A3[4] = fma2(xB.y, w45.x, A3[4]);
                A0[5] = fma2(xA.x, w45.y, A0[5]); A1[5] = fma2(xA.y, w45.y, A1[5]);
                A2[5] = fma2(xB.x, w45.y, A2[5]); A3[5] = fma2(xB.y, w45.y, A3[5]);
                A0[6] = fma2(xA.x, w67.x, A0[6]); A1[6] = fma2(xA.y, w67.x, A1[6]);
                A2[6] = fma2(xB.x, w67.x, A2[6]); A3[6] = fma2(xB.y, w67.x, A3[6]);
                A0[7] = fma2(xA.x, w67.y, A0[7]); A1[7] = fma2(xA.y, w67.y, A1[7]);
                A2[7] = fma2(xB.x, w67.y, A2[7]); A3[7] = fma2(xB.y, w67.y, A3[7]);
            }
        }
#pragma unroll
        for (int c = 0; c < COUT; c++) {
            float f0, f1, f2, f3, f4, f5, f6, f7;
            upk2(A0[c], f0, f1); upk2(A1[c], f2, f3);
            upk2(A2[c], f4, f5); upk2(A3[c], f6, f7);
            float4* p = (float4*)(ob + (size_t)c * NHWT);
            p[0] = make_float4(f0, f1, f2, f3);
            p[1] = make_float4(f4, f5, f6, f7);
        }
    } else {
#pragma unroll
        for (int kh = 0; kh < KS; kh++) {
#pragma unroll
            for (int kw = 0; kw < KS; kw++) {
                const int tap = kh * KS + kw;
                const u64* xp = &sx[((ty + kh) * HALO_W + (tx + kw)) * PSTRIDE];
                ulonglong2 xA = *(const ulonglong2*)(xp);
                ulonglong2 w01 = *(const ulonglong2*)&sw2[tap * COUT + 0];
                ulonglong2 w23 = *(const ulonglong2*)&sw2[tap * COUT + 2];
                ulonglong2 w45 = *(const ulonglong2*)&sw2[tap * COUT + 4];
                ulonglong2 w67 = *(const ulonglong2*)&sw2[tap * COUT + 6];
                A0[0] = fma2(xA.x, w01.x, A0[0]); A1[0] = fma2(xA.y, w01.x, A1[0]);
                A0[1] = fma2(xA.x, w01.y, A0[1]); A1[1] = fma2(xA.y, w01.y, A1[1]);
                A0[2] = fma2(xA.x, w23.x, A0[2]); A1[2] = fma2(xA.y, w23.x, A1[2]);
                A0[3] = fma2(xA.x, w23.y, A0[3]); A1[3] = fma2(xA.y, w23.y, A1[3]);
                A0[4] = fma2(xA.x, w45.x, A0[4]); A1[4] = fma2(xA.y, w45.x, A1[4]);
                A0[5] = fma2(xA.x, w45.y, A0[5]); A1[5] = fma2(xA.y, w45.y, A1[5]);
                A0[6] = fma2(xA.x, w67.x, A0[6]); A1[6] = fma2(xA.y, w67.x, A1[6]);
                A0[7] = fma2(xA.x, w67.y, A0[7]); A1[7] = fma2(xA.y, w67.y, A1[7]);
            }
        }
#pragma unroll
        for (int c = 0; c < COUT; c++) {
            float f0, f1, f2, f3;
            upk2(A0[c], f0, f1); upk2(A1[c], f2, f3);
            *(float4*)(ob + (size_t)c * NHWT) = make_float4(f0, f1, f2, f3);
        }
    }
}

// ============================ K2: recurrence ============================
// One thread per (b, c, h, w): stream 100 timesteps of Wx -> spikes.
#define K2THR 256

__global__ __launch_bounds__(K2THR)
void k2_rec(const float* __restrict__ thr_p, float* __restrict__ out)
{
    const size_t idx = (size_t)blockIdx.x * K2THR + threadIdx.x;  // over b*c*h*w
    const float thr = thr_p[0];

    const float4* src = (const float4*)g_wx + idx * (NT / 4);
    float4* dst = (float4*)out + idx * (NT / 4);

    float u = 0.0f;
    float4 cur = src[0];
#pragma unroll
    for (int j = 0; j < NT / 4; j++) {
        float4 nxt;
        if (j + 1 < NT / 4) nxt = src[j + 1];
        // exact reference recurrence: ut = (ut - st_prev*thr) + wx ; st = (ut > 0)
        float4 s;
        u = (u - (u > 0.f ? thr : 0.f)) + cur.x; s.x = (u > 0.f) ? 1.f : 0.f;
        u = (u - (u > 0.f ? thr : 0.f)) + cur.y; s.y = (u > 0.f) ? 1.f : 0.f;
        u = (u - (u > 0.f ? thr : 0.f)) + cur.z; s.z = (u > 0.f) ? 1.f : 0.f;
        u = (u - (u > 0.f ? thr : 0.f)) + cur.w; s.w = (u > 0.f) ? 1.f : 0.f;
        dst[j] = s;
        if (j + 1 < NT / 4) cur = nxt;
    }
}

extern "C" void kernel_launch(void* const* d_in, const int* in_sizes, int n_in,
                              void* d_out, int out_size)
{
    const float* x   = (const float*)d_in[0];  // [32,1,64,64,100]
    const float* w   = (const float*)d_in[1];  // [8,1,6,6]
    const float* thr = (const float*)d_in[2];  // [1]
    float* out = (float*)d_out;                // [32,8,64,64,100]

    // K1: conv into g_wx, one block per (tile, b, chunk)
    dim3 b1(TILE_W, TILE_H, 1);                         // 128 threads
    dim3 g1(NW / TILE_W, NH / TILE_H, NB * NCH);        // (4, 8, 416) = 13312 blocks
    k1_conv<<<g1, b1>>>(x, w);

    // K2: recurrence, one thread per (b, c, h, w)
    const size_t npix = (size_t)NB * COUT * NH * NW;    // 1048576
    k2_rec<<<(unsigned)(npix / K2THR), K2THR>>>(thr, out);
}

// round 13
// speedup vs baseline: 1.2541x; 1.2541x over previous
#include <cuda_runtime.h>

// Problem constants
#define NB    32
#define NH    64
#define NW    64
#define NT    100
#define COUT  8
#define KS    6
#define LP    2

#define TILE_W 16
#define TILE_H 8
#define HALO_W (TILE_W + KS - 1)   // 21
#define HALO_H (TILE_H + KS - 1)   // 13
#define NPIX   (HALO_W * HALO_H)   // 273
#define K1THR  128
#define NCH    13                  // chunks 0..11: 8 timesteps, chunk 12: 4
#define NHW    (NH * NW)           // 4096 pixels per (b, c) plane
#define NHWT   (NH * NW * NT)
#define PSTRIDE 6                  // u64 per pixel (48B): 16B-aligned cp16, conflict-free LDS.128

typedef unsigned long long u64;

// scratch, TRANSPOSED layout: plane index = ((b*NCH + ch)*COUT + c)*8 + tt,
// each plane is NHW floats (pixel-major -> coalesced for both K1 store & K2 load).
// size = 32*13*8*8*4096 floats = 436 MB
__device__ __align__(16) float g_wx[(size_t)NB * NCH * COUT * 8 * NHW];

__device__ __forceinline__ void upk2(u64 v, float& lo, float& hi) {
    asm("mov.b64 {%0, %1}, %2;" : "=f"(lo), "=f"(hi) : "l"(v));
}
__device__ __forceinline__ u64 fma2(u64 a, u64 b, u64 c) {
    u64 d; asm("fma.rn.f32x2 %0, %1, %2, %3;" : "=l"(d) : "l"(a), "l"(b), "l"(c)); return d;
}
__device__ __forceinline__ unsigned smem_u32(const void* p) {
    return (unsigned)__cvta_generic_to_shared(p);
}
__device__ __forceinline__ void cp16(unsigned dst, const void* src) {
    asm volatile("cp.async.ca.shared.global [%0], [%1], 16;" :: "r"(dst), "l"(src));
}
__device__ __forceinline__ void cp_commit() { asm volatile("cp.async.commit_group;" ::: "memory"); }
__device__ __forceinline__ void cp_wait0()  { asm volatile("cp.async.wait_group 0;" ::: "memory"); }

// ============================ K1: convolution ============================
// One block per (w-tile, h-tile, b, chunk): 13312 independent blocks.
__global__ __launch_bounds__(K1THR)
void k1_conv(const float* __restrict__ x,
             const float* __restrict__ w)
{
    __shared__ __align__(16) u64 sx[NPIX * PSTRIDE];
    __shared__ __align__(16) u64 sw2[KS * KS * COUT];   // tap-major, (w,w) duplicated

    const int tx    = threadIdx.x;
    const int ty    = threadIdx.y;
    const int tid   = tx + TILE_W * ty;
    const int b     = blockIdx.z / NCH;
    const int chunk = blockIdx.z % NCH;
    const int t0    = chunk * 8;
    const bool full = (chunk != NCH - 1);       // chunk 12 has 4 timesteps
    const int h0    = blockIdx.y * TILE_H;
    const int w0    = blockIdx.x * TILE_W;

    for (int i = tid; i < KS * KS * COUT; i += K1THR) {
        int tap = i >> 3, c = i & 7;
        unsigned bits = __float_as_uint(w[c * (KS * KS) + tap]);
        sw2[i] = ((u64)bits << 32) | (u64)bits;
    }

    const float* xb = x + (size_t)b * NH * NW * NT;
    const int n16 = full ? 2 : 1;
    for (int idx = tid; idx < NPIX * n16; idx += K1THR) {
        int pix = (n16 == 2) ? (idx >> 1) : idx;
        int j   = (n16 == 2) ? (idx & 1) : 0;
        int r = pix / HALO_W, c = pix % HALO_W;
        int gh = h0 - LP + r, gw = w0 - LP + c;
        if (gh >= 0 && gh < NH && gw >= 0 && gw < NW) {
            const float* src = xb + ((size_t)gh * NW + gw) * NT + t0 + j * 4;
            cp16(smem_u32(&sx[pix * PSTRIDE + j * 2]), src);
        } else {
            sx[pix * PSTRIDE + j * 2 + 0] = 0ull;
            sx[pix * PSTRIDE + j * 2 + 1] = 0ull;
        }
    }
    cp_commit();
    cp_wait0();
    __syncthreads();

    u64 A0[COUT], A1[COUT], A2[COUT], A3[COUT];
#pragma unroll
    for (int c = 0; c < COUT; c++) { A0[c] = 0; A1[c] = 0; A2[c] = 0; A3[c] = 0; }

    if (full) {
#pragma unroll
        for (int kh = 0; kh < KS; kh++) {
#pragma unroll
            for (int kw = 0; kw < KS; kw++) {
                const int tap = kh * KS + kw;
                const u64* xp = &sx[((ty + kh) * HALO_W + (tx + kw)) * PSTRIDE];
                ulonglong2 xA = *(const ulonglong2*)(xp);
                ulonglong2 xB = *(const ulonglong2*)(xp + 2);
                ulonglong2 w01 = *(const ulonglong2*)&sw2[tap * COUT + 0];
                ulonglong2 w23 = *(const ulonglong2*)&sw2[tap * COUT + 2];
                ulonglong2 w45 = *(const ulonglong2*)&sw2[tap * COUT + 4];
                ulonglong2 w67 = *(const ulonglong2*)&sw2[tap * COUT + 6];
                A0[0] = fma2(xA.x, w01.x, A0[0]); A1[0] = fma2(xA.y, w01.x, A1[0]);
                A2[0] = fma2(xB.x, w01.x, A2[0]); A3[0] = fma2(xB.y, w01.x, A3[0]);
                A0[1] = fma2(xA.x, w01.y, A0[1]); A1[1] = fma2(xA.y, w01.y, A1[1]);
                A2[1] = fma2(xB.x, w01.y, A2[1]); A3[1] = fma2(xB.y, w01.y, A3[1]);
                A0[2] = fma2(xA.x, w23.x, A0[2]); A1[2] = fma2(xA.y, w23.x, A1[2]);
                A2[2] = fma2(xB.x, w23.x, A2[2]); A3[2] = fma2(xB.y, w23.x, A3[2]);
                A0[3] = fma2(xA.x, w23.y, A0[3]); A1[3] = fma2(xA.y, w23.y, A1[3]);
                A2[3] = fma2(xB.x, w23.y, A2[3]); A3[3] = fma2(xB.y, w23.y, A3[3]);
                A0[4] = fma2(xA.x, w45.x, A0[4]); A1[4] = fma2(xA.y, w45.x, A1[4]);
                A2[4] = fma2(xB.x, w45.x, A2[4]); A3[4] = fma2(xB.y, w45.x, A3[4]);
                A0[5] = fma2(xA.x, w45.y, A0[5]); A1[5] = fma2(xA.y, w45.y, A1[5]);
                A2[5] = fma2(xB.x, w45.y, A2[5]); A3[5] = fma2(xB.y, w45.y, A3[5]);
                A0[6] = fma2(xA.x, w67.x, A0[6]); A1[6] = fma2(xA.y, w67.x, A1[6]);
                A2[6] = fma2(xB.x, w67.x, A2[6]); A3[6] = fma2(xB.y, w67.x, A3[6]);
                A0[7] = fma2(xA.x, w67.y, A0[7]); A1[7] = fma2(xA.y, w67.y, A1[7]);
                A2[7] = fma2(xB.x, w67.y, A2[7]); A3[7] = fma2(xB.y, w67.y, A3[7]);
            }
        }
    } else {
#pragma unroll
        for (int kh = 0; kh < KS; kh++) {
#pragma unroll
            for (int kw = 0; kw < KS; kw++) {
                const int tap = kh * KS + kw;
                const u64* xp = &sx[((ty + kh) * HALO_W + (tx + kw)) * PSTRIDE];
                ulonglong2 xA = *(const ulonglong2*)(xp);
                ulonglong2 w01 = *(const ulonglong2*)&sw2[tap * COUT + 0];
                ulonglong2 w23 = *(const ulonglong2*)&sw2[tap * COUT + 2];
                ulonglong2 w45 = *(const ulonglong2*)&sw2[tap * COUT + 4];
                ulonglong2 w67 = *(const ulonglong2*)&sw2[tap * COUT + 6];
                A0[0] = fma2(xA.x, w01.x, A0[0]); A1[0] = fma2(xA.y, w01.x, A1[0]);
                A0[1] = fma2(xA.x, w01.y, A0[1]); A1[1] = fma2(xA.y, w01.y, A1[1]);
                A0[2] = fma2(xA.x, w23.x, A0[2]); A1[2] = fma2(xA.y, w23.x, A1[2]);
                A0[3] = fma2(xA.x, w23.y, A0[3]); A1[3] = fma2(xA.y, w23.y, A1[3]);
                A0[4] = fma2(xA.x, w45.x, A0[4]); A1[4] = fma2(xA.y, w45.x, A1[4]);
                A0[5] = fma2(xA.x, w45.y, A0[5]); A1[5] = fma2(xA.y, w45.y, A1[5]);
                A0[6] = fma2(xA.x, w67.x, A0[6]); A1[6] = fma2(xA.y, w67.x, A1[6]);
                A0[7] = fma2(xA.x, w67.y, A0[7]); A1[7] = fma2(xA.y, w67.y, A1[7]);
            }
        }
    }

    // transposed store: plane = ((b*NCH+chunk)*COUT + c)*8 + tt, offset = pixel
    const int pix = (h0 + ty) * NW + (w0 + tx);
    float* pb = g_wx + ((size_t)((b * NCH + chunk) * COUT) * 8) * NHW + pix;
    const int ntt = full ? 8 : 4;
#pragma unroll
    for (int c = 0; c < COUT; c++) {
        float f[8];
        upk2(A0[c], f[0], f[1]); upk2(A1[c], f[2], f[3]);
        upk2(A2[c], f[4], f[5]); upk2(A3[c], f[6], f[7]);
        float* pc = pb + (size_t)c * 8 * NHW;
#pragma unroll
        for (int tt = 0; tt < 8; tt++) {
            if (tt < ntt) pc[(size_t)tt * NHW] = f[tt];   // warp-coalesced 4B stores
        }
    }
}

// ============================ K2: recurrence ============================
// One thread per (b, c, pixel); reads pixel-major planes (coalesced),
// writes t-contiguous float4 spikes (full sectors).
#define K2THR 256

__global__ __launch_bounds__(K2THR)
void k2_rec(const float* __restrict__ thr_p, float* __restrict__ out)
{
    const int bc  = blockIdx.x >> 4;            // b*8 + c   (0..255)
    const int pix = (blockIdx.x & 15) * K2THR + threadIdx.x;  // 0..4095
    const float thr = thr_p[0];

    // plane linear index: ((b*NCH + ch)*COUT + c)*8 + tt
    // = (b*NCH*COUT + c)*8*NHW ... with ch stride = COUT*8*NHW
    const int b = bc >> 3, c = bc & 7;
    const float* src0 = g_wx + ((size_t)((b * NCH) * COUT + c) * 8) * NHW + pix;
    const size_t chstride = (size_t)COUT * 8 * NHW;

    float* dst = out + ((size_t)bc * NHW + pix) * NT;

    float u = 0.0f;
    float cur[8], nxt[8];
#pragma unroll
    for (int tt = 0; tt < 8; tt++) cur[tt] = __ldcs(src0 + (size_t)tt * NHW);

#pragma unroll
    for (int ch = 0; ch < NCH; ch++) {
        const int nt = (ch == NCH - 1) ? 4 : 8;
        // prefetch next chunk (8 independent loads -> deep MLP)
        if (ch + 1 < NCH) {
            const float* sn = src0 + (size_t)(ch + 1) * chstride;
            const int nn = (ch + 1 == NCH - 1) ? 4 : 8;
#pragma unroll
            for (int tt = 0; tt < 8; tt++)
                if (tt < nn) nxt[tt] = __ldcs(sn + (size_t)tt * NHW);
        }
        // exact reference recurrence: ut = (ut - st_prev*thr) + wx ; st = (ut > 0)
        float s[8];
#pragma unroll
        for (int tt = 0; tt < 8; tt++) {
            if (tt < nt) {
                u = (u - (u > 0.f ? thr : 0.f)) + cur[tt];
                s[tt] = (u > 0.f) ? 1.f : 0.f;
            }
        }
        float4* p = (float4*)(dst + ch * 8);
        p[0] = make_float4(s[0], s[1], s[2], s[3]);
        if (nt == 8) p[1] = make_float4(s[4], s[5], s[6], s[7]);
#pragma unroll
        for (int tt = 0; tt < 8; tt++) cur[tt] = nxt[tt];
    }
}

extern "C" void kernel_launch(void* const* d_in, const int* in_sizes, int n_in,
                              void* d_out, int out_size)
{
    const float* x   = (const float*)d_in[0];  // [32,1,64,64,100]
    const float* w   = (const float*)d_in[1];  // [8,1,6,6]
    const float* thr = (const float*)d_in[2];  // [1]
    float* out = (float*)d_out;                // [32,8,64,64,100]

    dim3 b1(TILE_W, TILE_H, 1);                         // 128 threads
    dim3 g1(NW / TILE_W, NH / TILE_H, NB * NCH);        // 13312 blocks
    k1_conv<<<g1, b1>>>(x, w);

    k2_rec<<<4096, K2THR>>>(thr, out);                  // 1M threads
}

// round 14
// speedup vs baseline: 1.3286x; 1.0594x over previous
#include <cuda_runtime.h>

// Problem constants
#define NB    32
#define NH    64
#define NW    64
#define NT    100
#define COUT  8
#define KS    6
#define LP    2

#define TILE_W 16
#define TILE_H 8
#define HALO_W (TILE_W + KS - 1)   // 21
#define HALO_H (TILE_H + KS - 1)   // 13
#define NPIX   (HALO_W * HALO_H)   // 273
#define K1THR  128
#define NCH    13                  // chunks 0..11: 8 timesteps, chunk 12: 4
#define NHW    (NH * NW)           // 4096 pixels per (b, c) plane
#define NHWT   (NH * NW * NT)
#define PSTRIDE 6                  // u64 per pixel (48B): 16B-aligned cp16, conflict-free LDS.128

typedef unsigned long long u64;

// scratch, transposed: plane = ((b*NCH + ch)*COUT + c)*8 + tt, pixel-major planes
__device__ __align__(16) float g_wx[(size_t)NB * NCH * COUT * 8 * NHW];

__device__ __forceinline__ void upk2(u64 v, float& lo, float& hi) {
    asm("mov.b64 {%0, %1}, %2;" : "=f"(lo), "=f"(hi) : "l"(v));
}
__device__ __forceinline__ u64 fma2(u64 a, u64 b, u64 c) {
    u64 d; asm("fma.rn.f32x2 %0, %1, %2, %3;" : "=l"(d) : "l"(a), "l"(b), "l"(c)); return d;
}
__device__ __forceinline__ unsigned smem_u32(const void* p) {
    return (unsigned)__cvta_generic_to_shared(p);
}
__device__ __forceinline__ void cp16(unsigned dst, const void* src) {
    asm volatile("cp.async.ca.shared.global [%0], [%1], 16;" :: "r"(dst), "l"(src));
}
__device__ __forceinline__ void cp_commit() { asm volatile("cp.async.commit_group;" ::: "memory"); }
__device__ __forceinline__ void cp_wait0()  { asm volatile("cp.async.wait_group 0;" ::: "memory"); }

// ============================ K1: convolution ============================
// (unchanged from R12 -- bitwise-verified)
__global__ __launch_bounds__(K1THR)
void k1_conv(const float* __restrict__ x,
             const float* __restrict__ w)
{
    __shared__ __align__(16) u64 sx[NPIX * PSTRIDE];
    __shared__ __align__(16) u64 sw2[KS * KS * COUT];

    const int tx    = threadIdx.x;
    const int ty    = threadIdx.y;
    const int tid   = tx + TILE_W * ty;
    const int b     = blockIdx.z / NCH;
    const int chunk = blockIdx.z % NCH;
    const int t0    = chunk * 8;
    const bool full = (chunk != NCH - 1);
    const int h0    = blockIdx.y * TILE_H;
    const int w0    = blockIdx.x * TILE_W;

    for (int i = tid; i < KS * KS * COUT; i += K1THR) {
        int tap = i >> 3, c = i & 7;
        unsigned bits = __float_as_uint(w[c * (KS * KS) + tap]);
        sw2[i] = ((u64)bits << 32) | (u64)bits;
    }

    const float* xb = x + (size_t)b * NH * NW * NT;
    const int n16 = full ? 2 : 1;
    for (int idx = tid; idx < NPIX * n16; idx += K1THR) {
        int pix = (n16 == 2) ? (idx >> 1) : idx;
        int j   = (n16 == 2) ? (idx & 1) : 0;
        int r = pix / HALO_W, c = pix % HALO_W;
        int gh = h0 - LP + r, gw = w0 - LP + c;
        if (gh >= 0 && gh < NH && gw >= 0 && gw < NW) {
            const float* src = xb + ((size_t)gh * NW + gw) * NT + t0 + j * 4;
            cp16(smem_u32(&sx[pix * PSTRIDE + j * 2]), src);
        } else {
            sx[pix * PSTRIDE + j * 2 + 0] = 0ull;
            sx[pix * PSTRIDE + j * 2 + 1] = 0ull;
        }
    }
    cp_commit();
    cp_wait0();
    __syncthreads();

    u64 A0[COUT], A1[COUT], A2[COUT], A3[COUT];
#pragma unroll
    for (int c = 0; c < COUT; c++) { A0[c] = 0; A1[c] = 0; A2[c] = 0; A3[c] = 0; }

    if (full) {
#pragma unroll
        for (int kh = 0; kh < KS; kh++) {
#pragma unroll
            for (int kw = 0; kw < KS; kw++) {
                const int tap = kh * KS + kw;
                const u64* xp = &sx[((ty + kh) * HALO_W + (tx + kw)) * PSTRIDE];
                ulonglong2 xA = *(const ulonglong2*)(xp);
                ulonglong2 xB = *(const ulonglong2*)(xp + 2);
                ulonglong2 w01 = *(const ulonglong2*)&sw2[tap * COUT + 0];
                ulonglong2 w23 = *(const ulonglong2*)&sw2[tap * COUT + 2];
                ulonglong2 w45 = *(const ulonglong2*)&sw2[tap * COUT + 4];
                ulonglong2 w67 = *(const ulonglong2*)&sw2[tap * COUT + 6];
                A0[0] = fma2(xA.x, w01.x, A0[0]); A1[0] = fma2(xA.y, w01.x, A1[0]);
                A2[0] = fma2(xB.x, w01.x, A2[0]); A3[0] = fma2(xB.y, w01.x, A3[0]);
                A0[1] = fma2(xA.x, w01.y, A0[1]); A1[1] = fma2(xA.y, w01.y, A1[1]);
                A2[1] = fma2(xB.x, w01.y, A2[1]); A3[1] = fma2(xB.y, w01.y, A3[1]);
                A0[2] = fma2(xA.x, w23.x, A0[2]); A1[2] = fma2(xA.y, w23.x, A1[2]);
                A2[2] = fma2(xB.x, w23.x, A2[2]); A3[2] = fma2(xB.y, w23.x, A3[2]);
                A0[3] = fma2(xA.x, w23.y, A0[3]); A1[3] = fma2(xA.y, w23.y, A1[3]);
                A2[3] = fma2(xB.x, w23.y, A2[3]); A3[3] = fma2(xB.y, w23.y, A3[3]);
                A0[4] = fma2(xA.x, w45.x, A0[4]); A1[4] = fma2(xA.y, w45.x, A1[4]);
                A2[4] = fma2(xB.x, w45.x, A2[4]); A3[4] = fma2(xB.y, w45.x, A3[4]);
                A0[5] = fma2(xA.x, w45.y, A0[5]); A1[5] = fma2(xA.y, w45.y, A1[5]);
                A2[5] = fma2(xB.x, w45.y, A2[5]); A3[5] = fma2(xB.y, w45.y, A3[5]);
                A0[6] = fma2(xA.x, w67.x, A0[6]); A1[6] = fma2(xA.y, w67.x, A1[6]);
                A2[6] = fma2(xB.x, w67.x, A2[6]); A3[6] = fma2(xB.y, w67.x, A3[6]);
                A0[7] = fma2(xA.x, w67.y, A0[7]); A1[7] = fma2(xA.y, w67.y, A1[7]);
                A2[7] = fma2(xB.x, w67.y, A2[7]); A3[7] = fma2(xB.y, w67.y, A3[7]);
            }
        }
    } else {
#pragma unroll
        for (int kh = 0; kh < KS; kh++) {
#pragma unroll
            for (int kw = 0; kw < KS; kw++) {
                const int tap = kh * KS + kw;
                const u64* xp = &sx[((ty + kh) * HALO_W + (tx + kw)) * PSTRIDE];
                ulonglong2 xA = *(const ulonglong2*)(xp);
                ulonglong2 w01 = *(const ulonglong2*)&sw2[tap * COUT + 0];
                ulonglong2 w23 = *(const ulonglong2*)&sw2[tap * COUT + 2];
                ulonglong2 w45 = *(const ulonglong2*)&sw2[tap * COUT + 4];
                ulonglong2 w67 = *(const ulonglong2*)&sw2[tap * COUT + 6];
                A0[0] = fma2(xA.x, w01.x, A0[0]); A1[0] = fma2(xA.y, w01.x, A1[0]);
                A0[1] = fma2(xA.x, w01.y, A0[1]); A1[1] = fma2(xA.y, w01.y, A1[1]);
                A0[2] = fma2(xA.x, w23.x, A0[2]); A1[2] = fma2(xA.y, w23.x, A1[2]);
                A0[3] = fma2(xA.x, w23.y, A0[3]); A1[3] = fma2(xA.y, w23.y, A1[3]);
                A0[4] = fma2(xA.x, w45.x, A0[4]); A1[4] = fma2(xA.y, w45.x, A1[4]);
                A0[5] = fma2(xA.x, w45.y, A0[5]); A1[5] = fma2(xA.y, w45.y, A1[5]);
                A0[6] = fma2(xA.x, w67.x, A0[6]); A1[6] = fma2(xA.y, w67.x, A1[6]);
                A0[7] = fma2(xA.x, w67.y, A0[7]); A1[7] = fma2(xA.y, w67.y, A1[7]);
            }
        }
    }

    const int pix = (h0 + ty) * NW + (w0 + tx);
    float* pb = g_wx + ((size_t)((b * NCH + chunk) * COUT) * 8) * NHW + pix;
    const int ntt = full ? 8 : 4;
#pragma unroll
    for (int c = 0; c < COUT; c++) {
        float f[8];
        upk2(A0[c], f[0], f[1]); upk2(A1[c], f[2], f[3]);
        upk2(A2[c], f[4], f[5]); upk2(A3[c], f[6], f[7]);
        float* pc = pb + (size_t)c * 8 * NHW;
#pragma unroll
        for (int tt = 0; tt < 8; tt++) {
            if (tt < ntt) pc[(size_t)tt * NHW] = f[tt];
        }
    }
}

// ============================ K2: recurrence ============================
// Pipeline depth 3: 16 outstanding 128B lines per warp -> 2x bytes in flight.
#define K2THR 256

__global__ __launch_bounds__(K2THR)
void k2_rec(const float* __restrict__ thr_p, float* __restrict__ out)
{
    const int bc  = blockIdx.x >> 4;                          // b*8 + c
    const int pix = (blockIdx.x & 15) * K2THR + threadIdx.x;  // 0..4095
    const float thr = thr_p[0];

    const int b = bc >> 3, c = bc & 7;
    const float* src0 = g_wx + ((size_t)((b * NCH) * COUT + c) * 8) * NHW + pix;
    const size_t chs = (size_t)COUT * 8 * NHW;

    float* dst = out + ((size_t)bc * NHW + pix) * NT;

    float u = 0.0f;
    float cur[8], n1[8], n2[8];
#pragma unroll
    for (int tt = 0; tt < 8; tt++) cur[tt] = __ldcs(src0 + (size_t)tt * NHW);
#pragma unroll
    for (int tt = 0; tt < 8; tt++) n1[tt] = __ldcs(src0 + chs + (size_t)tt * NHW);

#pragma unroll
    for (int ch = 0; ch < NCH; ch++) {
        // prefetch chunk ch+2 (keeps ~16 lines outstanding)
        if (ch + 2 < NCH) {
            const float* sn = src0 + (size_t)(ch + 2) * chs;
            const int nn = (ch + 2 == NCH - 1) ? 4 : 8;
#pragma unroll
            for (int tt = 0; tt < 8; tt++)
                if (tt < nn) n2[tt] = __ldcs(sn + (size_t)tt * NHW);
        }

        const int nt = (ch == NCH - 1) ? 4 : 8;
        float s[8];
#pragma unroll
        for (int tt = 0; tt < 8; tt++) {
            if (tt < nt) {
                // exact reference: ut = (ut - st_prev*thr) + wx ; st = (ut > 0)
                u = (u - (u > 0.f ? thr : 0.f)) + cur[tt];
                s[tt] = (u > 0.f) ? 1.f : 0.f;
            }
        }
        // streaming stores: spikes are never re-read by this kernel
        __stcs((float4*)(dst + ch * 8), make_float4(s[0], s[1], s[2], s[3]));
        if (nt == 8)
            __stcs((float4*)(dst + ch * 8) + 1, make_float4(s[4], s[5], s[6], s[7]));

#pragma unroll
        for (int tt = 0; tt < 8; tt++) { cur[tt] = n1[tt]; n1[tt] = n2[tt]; }
    }
}

extern "C" void kernel_launch(void* const* d_in, const int* in_sizes, int n_in,
                              void* d_out, int out_size)
{
    const float* x   = (const float*)d_in[0];  // [32,1,64,64,100]
    const float* w   = (const float*)d_in[1];  // [8,1,6,6]
    const float* thr = (const float*)d_in[2];  // [1]
    float* out = (float*)d_out;                // [32,8,64,64,100]

    dim3 b1(TILE_W, TILE_H, 1);                         // 128 threads
    dim3 g1(NW / TILE_W, NH / TILE_H, NB * NCH);        // 13312 blocks
    k1_conv<<<g1, b1>>>(x, w);

    k2_rec<<<4096, K2THR>>>(thr, out);                  // 1M threads
}